// round 14
// baseline (speedup 1.0000x reference)
#include <cuda_runtime.h>
#include <cuda_fp16.h>
#include <cstdint>

// ---------------- problem constants ----------------
#define BB      2
#define LL      4096
#define DM      768
#define DIN     1536
#define NH      24
#define HD      64
#define DS      64
#define CONVD   1664          // DIN + 2*DS
#define DPROJ   3224          // 2*DIN + 2*DS + NH
#define BLROWS  (BB*LL)       // 8192
#define CHUNK   64
#define NCHUNK  (LL/CHUNK)    // 64

// single dynamic-smem symbol for the whole TU
extern __shared__ unsigned char dynsm[];

// ---------------- scratch ----------------
__device__ float g_zx   [(size_t)BLROWS*DPROJ];
__device__ float g_xbc  [(size_t)BLROWS*CONVD];
__device__ float g_dt   [(size_t)BLROWS*NH];
__device__ float g_dA   [(size_t)BLROWS*NH];
__device__ float g_S    [(size_t)BB*NH*NCHUNK*DS*HD];
__device__ float g_hini [(size_t)BB*NH*NCHUNK*DS*HD];
__device__ float g_P    [BB*NH*NCHUNK];
__device__ float g_y    [(size_t)BLROWS*DIN];

// fp16 operands
__device__ __half g_xh [(size_t)BLROWS*DM];
__device__ __half g_wih[(size_t)DPROJ*DM];      // W_in^T  [N][K] fp16
__device__ __half g_yh [(size_t)BLROWS*DIN];
__device__ __half g_woh[(size_t)DM*DIN];        // W_out^T [N][K] fp16

// ======================= convert helpers ===================================
__global__ void __launch_bounds__(256) split_x_k(
    const float* __restrict__ X, __half* __restrict__ Xh, int n4)
{
    int i = blockIdx.x * blockDim.x + threadIdx.x;
    if (i >= n4) return;
    float4 v = reinterpret_cast<const float4*>(X)[i];
    __half2 hh0{__float2half(v.x), __float2half(v.y)};
    __half2 hh1{__float2half(v.z), __float2half(v.w)};
    reinterpret_cast<__half2*>(Xh)[i * 2 + 0] = hh0;
    reinterpret_cast<__half2*>(Xh)[i * 2 + 1] = hh1;
}

__global__ void __launch_bounds__(256) tsplit_k(
    const float* __restrict__ W, __half* __restrict__ Th, int K, int N)
{
    __shared__ float tile[32][33];
    int k0 = blockIdx.x * 32, n0 = blockIdx.y * 32;
    int tx = threadIdx.x % 32, ty = threadIdx.x / 32;
#pragma unroll
    for (int i = ty; i < 32; i += 8) {
        int k = k0 + i, n = n0 + tx;
        tile[i][tx] = (k < K && n < N) ? W[(size_t)k * N + n] : 0.f;
    }
    __syncthreads();
#pragma unroll
    for (int i = ty; i < 32; i += 8) {
        int n = n0 + i, k = k0 + tx;
        if (n < N && k < K)
            Th[(size_t)n * K + k] = __float2half(tile[tx][i]);
    }
}

// ======================= mma helpers =======================================
__device__ __forceinline__ void cp16(uint32_t s, const void* g, bool pred) {
    int sz = pred ? 16 : 0;
    asm volatile("cp.async.cg.shared.global [%0], [%1], 16, %2;\n"
                 :: "r"(s), "l"(g), "r"(sz));
}
__device__ __forceinline__ void mma_fp16(float* d, const uint32_t* a, const uint32_t* b) {
    asm volatile("mma.sync.aligned.m16n8k16.row.col.f32.f16.f16.f32 "
                 "{%0,%1,%2,%3}, {%4,%5,%6,%7}, {%8,%9}, {%0,%1,%2,%3};"
                 : "+f"(d[0]), "+f"(d[1]), "+f"(d[2]), "+f"(d[3])
                 : "r"(a[0]), "r"(a[1]), "r"(a[2]), "r"(a[3]), "r"(b[0]), "r"(b[1]));
}
__device__ __forceinline__ void ldsm4(uint32_t* r, uint32_t a) {
    asm volatile("ldmatrix.sync.aligned.m8n8.x4.shared.b16 {%0,%1,%2,%3}, [%4];"
                 : "=r"(r[0]), "=r"(r[1]), "=r"(r[2]), "=r"(r[3]) : "r"(a));
}

// ======================= tensor-core fp16 GEMM =============================
#define GSTRIDE 40
#define BPART   (128*GSTRIDE)

template <int BM, int NT>
__global__ void __launch_bounds__(NT) mma_gemm_k(
    const __half* __restrict__ Ah, const __half* __restrict__ Bh,
    float* __restrict__ C, int Nn, int K)
{
    constexpr int APART = BM * GSTRIDE;
    constexpr int STAGE_BYTES = (APART + BPART) * 2;
    constexpr int AROWS_PER_STEP = NT / 4;
    constexpr int NA = BM / AROWS_PER_STEP;
    constexpr int NB = 128 / AROWS_PER_STEP;

    const int tid  = threadIdx.x;
    const int lane = tid & 31;
    const int wid  = tid >> 5;
    const int wm   = wid >> 2;
    const int wn   = wid & 3;
    const int g    = lane >> 2;
    const int tig  = lane & 3;

    const int row0 = blockIdx.y * BM;
    const int col0 = blockIdx.x * 128;
    const int iters = K / 32;
    const int r0 = tid >> 2, s0 = tid & 3;

    const int arow = (lane & 7) + ((lane >> 3) & 1) * 8;
    const int acol = ((lane >> 4) & 1) * 8;
    const int brow = (lane & 7) + ((lane >> 4) & 1) * 8;
    const int bcol = ((lane >> 3) & 1) * 8;

    const uint32_t smbase = (uint32_t)__cvta_generic_to_shared(dynsm);
    uint32_t aoff[4], boff[2];
#pragma unroll
    for (int mi = 0; mi < 4; mi++)
        aoff[mi] = (uint32_t)(((wm * 64 + mi * 16 + arow) * GSTRIDE + acol) * 2);
#pragma unroll
    for (int nj = 0; nj < 2; nj++)
        boff[nj] = (uint32_t)(((wn * 32 + nj * 16 + brow) * GSTRIDE + bcol) * 2);

    float acc[4][4][4];
#pragma unroll
    for (int mi = 0; mi < 4; mi++)
#pragma unroll
        for (int ni = 0; ni < 4; ni++)
#pragma unroll
            for (int q = 0; q < 4; q++) acc[mi][ni][q] = 0.f;

    auto load_tiles = [&](int buf, int it) {
        const int k0 = it * 32;
        uint32_t b = smbase + buf * STAGE_BYTES;
#pragma unroll
        for (int j = 0; j < NA; j++) {
            int r = r0 + j * AROWS_PER_STEP;
            uint32_t soff = (uint32_t)(r * GSTRIDE + s0 * 8) * 2;
            size_t ga = (size_t)(row0 + r) * K + k0 + s0 * 8;
            cp16(b + soff, Ah + ga, true);
        }
#pragma unroll
        for (int j = 0; j < NB; j++) {
            int r = (r0 + j * AROWS_PER_STEP) & 127;
            if (NB == 2 || r0 < 128) {
                uint32_t soff = (uint32_t)(r * GSTRIDE + s0 * 8) * 2;
                int nb = col0 + r;
                bool p = nb < Nn;
                size_t gb = (size_t)(p ? nb : 0) * K + k0 + s0 * 8;
                cp16(b + APART * 2 + soff, Bh + gb, p);
            }
        }
        asm volatile("cp.async.commit_group;\n" ::);
    };

    load_tiles(0, 0);
    load_tiles(1, 1);

    for (int it = 0; it < iters; it++) {
        asm volatile("cp.async.wait_group 1;\n" ::);
        __syncthreads();

        const int buf = it % 3;
        uint32_t bA  = smbase + buf * STAGE_BYTES;
        uint32_t bBh = bA + APART * 2;

#pragma unroll
        for (int kk = 0; kk < 2; kk++) {
            const uint32_t kof = kk * 32;
            uint32_t ah[4][4], bh[2][4];
#pragma unroll
            for (int mi = 0; mi < 4; mi++) ldsm4(ah[mi], bA + aoff[mi] + kof);
#pragma unroll
            for (int nj = 0; nj < 2; nj++) ldsm4(bh[nj], bBh + boff[nj] + kof);

#pragma unroll
            for (int mi = 0; mi < 4; mi++)
#pragma unroll
                for (int ni = 0; ni < 4; ni++)
                    mma_fp16(acc[mi][ni], ah[mi], &bh[ni >> 1][(ni & 1) * 2]);
        }

        const int nx = it + 2;
        if (nx < iters) {
            load_tiles(nx % 3, nx);
        } else {
            asm volatile("cp.async.commit_group;\n" ::);
        }
    }

#pragma unroll
    for (int mi = 0; mi < 4; mi++) {
        int ra = row0 + wm * 64 + mi * 16 + g;
#pragma unroll
        for (int ni = 0; ni < 4; ni++) {
            int c = col0 + wn * 32 + ni * 8 + 2 * tig;
            if (c < Nn) {
                *reinterpret_cast<float2*>(&C[(size_t)ra * Nn + c]) =
                    make_float2(acc[mi][ni][0], acc[mi][ni][1]);
                *reinterpret_cast<float2*>(&C[(size_t)(ra + 8) * Nn + c]) =
                    make_float2(acc[mi][ni][2], acc[mi][ni][3]);
            }
        }
    }
}

#define SMEM_BM256 (3 * (256 * GSTRIDE + 128 * GSTRIDE) * 2)   // 92160
#define SMEM_BM128 (3 * (128 * GSTRIDE + 128 * GSTRIDE) * 2)   // 61440

// ---------------- conv: smem-tiled depthwise causal conv + silu -------------
__global__ void __launch_bounds__(256) conv_k(
    const float* __restrict__ conv_w, const float* __restrict__ conv_b)
{
    __shared__ float st[35][128];
    const int c0 = blockIdx.x * 128;
    const int b  = blockIdx.y >> 7;
    const int lg = blockIdx.y & 127;
    const int l0 = lg * 32;

    for (int i = threadIdx.x; i < 35 * 128; i += 256) {
        int r = i >> 7, cc = i & 127;
        int ls = l0 - 3 + r;
        st[r][cc] = (ls >= 0) ? g_zx[(size_t)(b * LL + ls) * DPROJ + DIN + c0 + cc] : 0.f;
    }
    __syncthreads();

    for (int i = threadIdx.x; i < 32 * 128; i += 256) {
        int r = i >> 7, cc = i & 127;
        int c = c0 + cc;
        float w0 = conv_w[c * 4 + 0], w1 = conv_w[c * 4 + 1];
        float w2 = conv_w[c * 4 + 2], w3 = conv_w[c * 4 + 3];
        float acc = conv_b[c];
        acc = fmaf(st[r + 0][cc], w0, acc);
        acc = fmaf(st[r + 1][cc], w1, acc);
        acc = fmaf(st[r + 2][cc], w2, acc);
        acc = fmaf(st[r + 3][cc], w3, acc);
        g_xbc[(size_t)(b * LL + l0 + r) * CONVD + c] = acc / (1.f + __expf(-acc));
    }
}

// ---------------- dt prep ----------------------------------------------------
__global__ void __launch_bounds__(256) dt_k(
    const float* __restrict__ dt_bias, const float* __restrict__ A_log)
{
    int i = blockIdx.x * blockDim.x + threadIdx.x;
    if (i >= BLROWS * NH) return;
    int row = i / NH, h = i % NH;
    float v = g_zx[(size_t)row * DPROJ + (DIN + CONVD) + h] + dt_bias[h];
    float sp = (v > 20.f) ? v : log1pf(expf(v));
    float Ah = -expf(A_log[h]);
    g_dt[i] = sp;
    g_dA[i] = expf(sp * Ah);
}

// ======================= SSD scan (tensor-core) =============================
// ssd1: per (b,h,chunk): H_end[n,p] = sum_s rsuf_s * B[s,n] * dt_s * x_s[p]
//   via one 64x64x64 fp16 GEMM. Also writes g_P.
// combine (unchanged fp32) -> g_hini.
// ssd2: Y = [G | cum*C] @ [U | Hini]^T + D*x, where G[t,s] = (C_t.B_s)*decay(t,s).
// Decay tables via running products (no expf).

#define SSD1_SMEM 36096
__global__ void __launch_bounds__(128) ssd1_k()
{
    const int bid = blockIdx.x;
    const int h = bid % NH;
    const int c = (bid / NH) % NCHUNK;
    const int b = bid / (NH * NCHUNK);
    const int rowbase = b * LL + c * CHUNK;
    __half* sBt = reinterpret_cast<__half*>(dynsm);            // [64 n][72 s]
    __half* sUt = reinterpret_cast<__half*>(dynsm + 9216);     // [64 p][72 s]
    float* sdt  = reinterpret_cast<float*>(dynsm + 18432);
    float* sdA  = reinterpret_cast<float*>(dynsm + 18688);
    float* rsf  = reinterpret_cast<float*>(dynsm + 18944);
    float* hb   = reinterpret_cast<float*>(dynsm + 19200);     // [64][66]
    const int tid = threadIdx.x, lane = tid & 31, w = tid >> 5;

    if (tid < 64) {
        sdt[tid] = g_dt[(size_t)(rowbase + tid) * NH + h];
        sdA[tid] = g_dA[(size_t)(rowbase + tid) * NH + h];
    }
    __syncthreads();
    if (tid < 64) {
        float rr = 1.f;
        for (int j = 63; j > tid; j--) rr *= sdA[j];   // prod_{j=tid+1..63}
        rsf[tid] = rr;
    }
    __syncthreads();
    for (int i = tid; i < 4096; i += 128) {
        int s = i >> 6, n = i & 63;
        const float* xr = g_xbc + (size_t)(rowbase + s) * CONVD;
        sBt[n * 72 + s] = __float2half(rsf[s] * xr[DIN + n]);
        sUt[n * 72 + s] = __float2half(sdt[s] * xr[h * HD + n]);   // n plays p
    }
    __syncthreads();

    const int g = lane >> 2, tig = lane & 3;
    const int arow = (lane & 7) + ((lane >> 3) & 1) * 8;
    const int acol = ((lane >> 4) & 1) * 8;
    const int brow = (lane & 7) + ((lane >> 4) & 1) * 8;
    const int bcol = ((lane >> 3) & 1) * 8;
    const int tb = w * 16;
    const uint32_t base = (uint32_t)__cvta_generic_to_shared(dynsm);

    float acc[8][4];
#pragma unroll
    for (int i = 0; i < 8; i++)
#pragma unroll
        for (int q = 0; q < 4; q++) acc[i][q] = 0.f;
#pragma unroll
    for (int k = 0; k < 4; k++) {
        uint32_t af[4];
        ldsm4(af, base + (uint32_t)(((tb + arow) * 72 + k * 16 + acol) * 2));
#pragma unroll
        for (int pj = 0; pj < 4; pj++) {
            uint32_t bf[4];
            ldsm4(bf, base + 9216u + (uint32_t)(((pj * 16 + brow) * 72 + k * 16 + bcol) * 2));
            mma_fp16(acc[pj * 2 + 0], af, &bf[0]);
            mma_fp16(acc[pj * 2 + 1], af, &bf[2]);
        }
    }
    const int n0 = tb + g, n1 = tb + g + 8;
#pragma unroll
    for (int ni = 0; ni < 8; ni++) {
        int p0 = ni * 8 + 2 * tig;
        hb[n0 * 66 + p0]     = acc[ni][0];
        hb[n0 * 66 + p0 + 1] = acc[ni][1];
        hb[n1 * 66 + p0]     = acc[ni][2];
        hb[n1 * 66 + p0 + 1] = acc[ni][3];
    }
    __syncthreads();
    const size_t bhc = ((size_t)(b * NH + h)) * NCHUNK + c;
    float* Sp = g_S + bhc * DS * HD;
    for (int i = tid; i < 4096; i += 128) {
        int n = i >> 6, p = i & 63;
        Sp[n * HD + p] = hb[n * 66 + p];
    }
    if (tid == 0) g_P[bhc] = rsf[0] * sdA[0];
}

// ---------------- combine (unchanged) ----------------------------------------
__global__ void __launch_bounds__(256) combine_k()
{
    const int i = blockIdx.x * blockDim.x + threadIdx.x;
    if (i >= BB * NH * DS * HD) return;
    const int pn = i % (DS * HD);
    const int bh = i / (DS * HD);
    float hp = 0.f;
    const float* P = g_P + bh * NCHUNK;
    const size_t base = (size_t)bh * NCHUNK * DS * HD + pn;
    for (int c = 0; c < NCHUNK; c++) {
        g_hini[base + (size_t)c * DS * HD] = hp;
        hp = fmaf(hp, P[c], g_S[base + (size_t)c * DS * HD]);
    }
}

#define SSD2_SMEM 71424
__global__ void __launch_bounds__(128) ssd2_k(const float* __restrict__ Dp)
{
    const int bid = blockIdx.x;
    const int h = bid % NH;
    const int c = (bid / NH) % NCHUNK;
    const int b = bid / (NH * NCHUNK);
    const int rowbase = b * LL + c * CHUNK;
    const size_t bhc = ((size_t)(b * NH + h)) * NCHUNK + c;

    __half* sB  = reinterpret_cast<__half*>(dynsm);             // [64 t][72 n]
    __half* sC  = reinterpret_cast<__half*>(dynsm + 9216);      // [64 t][72 n]
    float*  sR  = reinterpret_cast<float*>(dynsm + 18432);      // [64 t][68 s]
    __half* sGE = reinterpret_cast<__half*>(dynsm + 35840);     // [64 t][136] A'
    __half* sBp = reinterpret_cast<__half*>(dynsm + 53248);     // [64 p][136] B'
    float*  sdt = reinterpret_cast<float*>(dynsm + 70656);
    float*  sdA = reinterpret_cast<float*>(dynsm + 70912);
    float*  scum= reinterpret_cast<float*>(dynsm + 71168);
    float*  ybuf= reinterpret_cast<float*>(dynsm);              // alias sB/sC [64][66]
    const int tid = threadIdx.x, lane = tid & 31, w = tid >> 5;

    if (tid < 64) {
        sdt[tid] = g_dt[(size_t)(rowbase + tid) * NH + h];
        sdA[tid] = g_dA[(size_t)(rowbase + tid) * NH + h];
    }
    __syncthreads();
    if (tid < 64) {
        int t = tid;
        float rr = 1.f;
        sR[t * 68 + t] = 1.f;
        for (int s = t - 1; s >= 0; s--) { rr *= sdA[s + 1]; sR[t * 68 + s] = rr; }
        scum[t] = rr * sdA[0];
    }
    for (int i = tid; i < 4096; i += 128) {
        int t = i >> 6, n = i & 63;
        const float* xr = g_xbc + (size_t)(rowbase + t) * CONVD;
        sB[t * 72 + n] = __float2half(xr[DIN + n]);
        sC[t * 72 + n] = __float2half(xr[DIN + DS + n]);
    }
    __syncthreads();
    for (int i = tid; i < 4096; i += 128) {
        int s = i >> 6, p = i & 63;
        const float* xr = g_xbc + (size_t)(rowbase + s) * CONVD;
        sBp[p * 136 + s] = __float2half(sdt[s] * xr[h * HD + p]);
    }
    {
        const float* hv = g_hini + bhc * DS * HD;
        for (int i = tid; i < 4096; i += 128) {
            int n = i >> 6, p = i & 63;
            sBp[p * 136 + 64 + n] = __float2half(hv[n * HD + p]);
        }
    }
    __syncthreads();

    const int g = lane >> 2, tig = lane & 3;
    const int arow = (lane & 7) + ((lane >> 3) & 1) * 8;
    const int acol = ((lane >> 4) & 1) * 8;
    const int brow = (lane & 7) + ((lane >> 4) & 1) * 8;
    const int bcol = ((lane >> 3) & 1) * 8;
    const int tb = w * 16;
    const uint32_t base = (uint32_t)__cvta_generic_to_shared(dynsm);

    // S = C @ B^T
    float accS[8][4];
#pragma unroll
    for (int i = 0; i < 8; i++)
#pragma unroll
        for (int q = 0; q < 4; q++) accS[i][q] = 0.f;
#pragma unroll
    for (int k = 0; k < 4; k++) {
        uint32_t af[4];
        ldsm4(af, base + 9216u + (uint32_t)(((tb + arow) * 72 + k * 16 + acol) * 2));
#pragma unroll
        for (int nj = 0; nj < 4; nj++) {
            uint32_t bf[4];
            ldsm4(bf, base + (uint32_t)(((nj * 16 + brow) * 72 + k * 16 + bcol) * 2));
            mma_fp16(accS[nj * 2 + 0], af, &bf[0]);
            mma_fp16(accS[nj * 2 + 1], af, &bf[2]);
        }
    }
    // mask + decay -> G (cols 0..63 of A')
    const int t0 = tb + g, t1 = tb + g + 8;
#pragma unroll
    for (int ni = 0; ni < 8; ni++) {
        int s0 = ni * 8 + 2 * tig;
        float r00 = (s0     <= t0) ? sR[t0 * 68 + s0]     : 0.f;
        float r01 = (s0 + 1 <= t0) ? sR[t0 * 68 + s0 + 1] : 0.f;
        float r10 = (s0     <= t1) ? sR[t1 * 68 + s0]     : 0.f;
        float r11 = (s0 + 1 <= t1) ? sR[t1 * 68 + s0 + 1] : 0.f;
        __half2 h0 = __floats2half2_rn(accS[ni][0] * r00, accS[ni][1] * r01);
        __half2 h1 = __floats2half2_rn(accS[ni][2] * r10, accS[ni][3] * r11);
        *reinterpret_cast<__half2*>(sGE + t0 * 136 + s0) = h0;
        *reinterpret_cast<__half2*>(sGE + t1 * 136 + s0) = h1;
    }
    // Ce = cum_t * C (cols 64..127 of A')
    for (int i = tid; i < 4096; i += 128) {
        int t = i >> 6, n = i & 63;
        sGE[t * 136 + 64 + n] = __float2half(__half2float(sC[t * 72 + n]) * scum[t]);
    }
    __syncthreads();

    // Y = A' @ B'^T  (k = 128)
    float accY[8][4];
#pragma unroll
    for (int i = 0; i < 8; i++)
#pragma unroll
        for (int q = 0; q < 4; q++) accY[i][q] = 0.f;
#pragma unroll
    for (int k = 0; k < 8; k++) {
        uint32_t af[4];
        ldsm4(af, base + 35840u + (uint32_t)(((tb + arow) * 136 + k * 16 + acol) * 2));
#pragma unroll
        for (int pj = 0; pj < 4; pj++) {
            uint32_t bf[4];
            ldsm4(bf, base + 53248u + (uint32_t)(((pj * 16 + brow) * 136 + k * 16 + bcol) * 2));
            mma_fp16(accY[pj * 2 + 0], af, &bf[0]);
            mma_fp16(accY[pj * 2 + 1], af, &bf[2]);
        }
    }
#pragma unroll
    for (int ni = 0; ni < 8; ni++) {
        int p0 = ni * 8 + 2 * tig;
        ybuf[t0 * 66 + p0]     = accY[ni][0];
        ybuf[t0 * 66 + p0 + 1] = accY[ni][1];
        ybuf[t1 * 66 + p0]     = accY[ni][2];
        ybuf[t1 * 66 + p0 + 1] = accY[ni][3];
    }
    __syncthreads();
    const float Dh = Dp[h];
    for (int i = tid; i < 4096; i += 128) {
        int t = i >> 6, p = i & 63;
        float x = g_xbc[(size_t)(rowbase + t) * CONVD + h * HD + p];
        g_y[(size_t)(rowbase + t) * DIN + h * HD + p] = ybuf[t * 66 + p] + Dh * x;
    }
}

// ---------------- gate + RMSNorm + convert to fp16 --------------------------
__global__ void __launch_bounds__(512) gatenorm_k(const float* __restrict__ norm_w)
{
    const int row = blockIdx.x;
    const float* zrow = g_zx + (size_t)row * DPROJ;
    const float* yrow = g_y + (size_t)row * DIN;

    float gv[3];
    float ss = 0.f;
#pragma unroll
    for (int j = 0; j < 3; j++) {
        int i = threadIdx.x + j * 512;
        float z = zrow[i];
        float gg = yrow[i] * (z / (1.f + __expf(-z)));
        gv[j] = gg;
        ss = fmaf(gg, gg, ss);
    }

    __shared__ float red[16];
#pragma unroll
    for (int o = 16; o; o >>= 1) ss += __shfl_xor_sync(0xffffffffu, ss, o);
    if ((threadIdx.x & 31) == 0) red[threadIdx.x >> 5] = ss;
    __syncthreads();
    if (threadIdx.x < 16) {
        float v = red[threadIdx.x];
#pragma unroll
        for (int o = 8; o; o >>= 1) v += __shfl_xor_sync(0x0000ffffu, v, o);
        if (threadIdx.x == 0) red[0] = v;
    }
    __syncthreads();
    const float scale = rsqrtf(red[0] / (float)DIN + 1e-5f);
#pragma unroll
    for (int j = 0; j < 3; j++) {
        int i = threadIdx.x + j * 512;
        float v = gv[j] * scale * norm_w[i];
        g_yh[(size_t)row * DIN + i] = __float2half(v);
    }
}

// ---------------- launch ----------------------------------------------------
extern "C" void kernel_launch(void* const* d_in, const int* in_sizes, int n_in,
                              void* d_out, int out_size)
{
    const float* x       = (const float*)d_in[0];
    const float* W_in    = (const float*)d_in[1];
    const float* conv_w  = (const float*)d_in[2];
    const float* conv_b  = (const float*)d_in[3];
    const float* dt_bias = (const float*)d_in[4];
    const float* A_log   = (const float*)d_in[5];
    const float* Dp      = (const float*)d_in[6];
    const float* norm_w  = (const float*)d_in[7];
    const float* W_out   = (const float*)d_in[8];
    float* out           = (float*)d_out;

    float* zx = nullptr;
    __half *xh, *wih, *yh, *woh;
    cudaGetSymbolAddress((void**)&zx,  g_zx);
    cudaGetSymbolAddress((void**)&xh,  g_xh);
    cudaGetSymbolAddress((void**)&wih, g_wih);
    cudaGetSymbolAddress((void**)&yh,  g_yh);
    cudaGetSymbolAddress((void**)&woh, g_woh);

    static bool attr_set = false;
    if (!attr_set) {
        cudaFuncSetAttribute(mma_gemm_k<256, 512>,
                             cudaFuncAttributeMaxDynamicSharedMemorySize, SMEM_BM256);
        cudaFuncSetAttribute(mma_gemm_k<128, 256>,
                             cudaFuncAttributeMaxDynamicSharedMemorySize, SMEM_BM128);
        cudaFuncSetAttribute(ssd1_k, cudaFuncAttributeMaxDynamicSharedMemorySize,
                             SSD1_SMEM);
        cudaFuncSetAttribute(ssd2_k, cudaFuncAttributeMaxDynamicSharedMemorySize,
                             SSD2_SMEM);
        attr_set = true;
    }

    // 0) convert inputs to fp16
    {
        int n4 = BLROWS * DM / 4;
        split_x_k<<<(n4 + 255) / 256, 256>>>(x, xh, n4);
        tsplit_k<<<dim3(DM / 32, (DPROJ + 31) / 32), 256>>>(W_in, wih, DM, DPROJ);
        tsplit_k<<<dim3(DIN / 32, DM / 32), 256>>>(W_out, woh, DIN, DM);
    }

    // 1) zxbcdt = x @ W_in
    mma_gemm_k<256, 512><<<dim3((DPROJ + 127) / 128, BLROWS / 256), 512, SMEM_BM256>>>(
        xh, wih, zx, DPROJ, DM);

    // 2) conv + silu ; dt prep
    conv_k<<<dim3(CONVD / 128, BB * (LL / 32)), 256>>>(conv_w, conv_b);
    dt_k<<<(BLROWS * NH + 255) / 256, 256>>>(dt_bias, A_log);

    // 3) SSD chunked scan (tensor cores)
    {
        int blocks = BB * NCHUNK * NH;   // 3072, h fastest for L2 reuse
        ssd1_k<<<blocks, 128, SSD1_SMEM>>>();
        int nstates = BB * NH * DS * HD;
        combine_k<<<(nstates + 255) / 256, 256>>>();
        ssd2_k<<<blocks, 128, SSD2_SMEM>>>(Dp);
    }

    // 4) gate + RMSNorm + fp16 convert
    gatenorm_k<<<BLROWS, 512>>>(norm_w);

    // 5) out = y @ W_out
    mma_gemm_k<128, 256><<<dim3(DM / 128, BLROWS / 128), 256, SMEM_BM128>>>(
        yh, woh, out, DM, DIN);
}

// round 15
// speedup vs baseline: 1.0975x; 1.0975x over previous
#include <cuda_runtime.h>
#include <cuda_fp16.h>
#include <cstdint>

// ---------------- problem constants ----------------
#define BB      2
#define LL      4096
#define DM      768
#define DIN     1536
#define NH      24
#define HD      64
#define DS      64
#define CONVD   1664          // DIN + 2*DS
#define DPROJ   3224          // 2*DIN + 2*DS + NH
#define BLROWS  (BB*LL)       // 8192
#define CHUNK   64
#define NCHUNK  (LL/CHUNK)    // 64

// single dynamic-smem symbol for the whole TU
extern __shared__ unsigned char dynsm[];

// ---------------- scratch ----------------
__device__ float g_zx   [(size_t)BLROWS*DPROJ];
__device__ float g_xbc  [(size_t)BLROWS*CONVD];
__device__ float g_dt   [(size_t)BLROWS*NH];
__device__ float g_dA   [(size_t)BLROWS*NH];
__device__ float g_S    [(size_t)BB*NH*NCHUNK*DS*HD];
__device__ float g_hini [(size_t)BB*NH*NCHUNK*DS*HD];
__device__ float g_P    [BB*NH*NCHUNK];
__device__ float g_y    [(size_t)BLROWS*DIN];

// fp16 operands
__device__ __half g_xh [(size_t)BLROWS*DM];
__device__ __half g_wih[(size_t)DPROJ*DM];      // W_in^T  [N][K] fp16
__device__ __half g_yh [(size_t)BLROWS*DIN];
__device__ __half g_woh[(size_t)DM*DIN];        // W_out^T [N][K] fp16

// ======================= convert helpers ===================================
__global__ void __launch_bounds__(256) split_x_k(
    const float* __restrict__ X, __half* __restrict__ Xh, int n4)
{
    int i = blockIdx.x * blockDim.x + threadIdx.x;
    if (i >= n4) return;
    float4 v = reinterpret_cast<const float4*>(X)[i];
    __half2 hh0{__float2half(v.x), __float2half(v.y)};
    __half2 hh1{__float2half(v.z), __float2half(v.w)};
    reinterpret_cast<__half2*>(Xh)[i * 2 + 0] = hh0;
    reinterpret_cast<__half2*>(Xh)[i * 2 + 1] = hh1;
}

__global__ void __launch_bounds__(256) tsplit_k(
    const float* __restrict__ W, __half* __restrict__ Th, int K, int N)
{
    __shared__ float tile[32][33];
    int k0 = blockIdx.x * 32, n0 = blockIdx.y * 32;
    int tx = threadIdx.x % 32, ty = threadIdx.x / 32;
#pragma unroll
    for (int i = ty; i < 32; i += 8) {
        int k = k0 + i, n = n0 + tx;
        tile[i][tx] = (k < K && n < N) ? W[(size_t)k * N + n] : 0.f;
    }
    __syncthreads();
#pragma unroll
    for (int i = ty; i < 32; i += 8) {
        int n = n0 + i, k = k0 + tx;
        if (n < N && k < K)
            Th[(size_t)n * K + k] = __float2half(tile[tx][i]);
    }
}

// ======================= mma helpers =======================================
__device__ __forceinline__ void cp16(uint32_t s, const void* g, bool pred) {
    int sz = pred ? 16 : 0;
    asm volatile("cp.async.cg.shared.global [%0], [%1], 16, %2;\n"
                 :: "r"(s), "l"(g), "r"(sz));
}
__device__ __forceinline__ void mma_fp16(float* d, const uint32_t* a, const uint32_t* b) {
    asm volatile("mma.sync.aligned.m16n8k16.row.col.f32.f16.f16.f32 "
                 "{%0,%1,%2,%3}, {%4,%5,%6,%7}, {%8,%9}, {%0,%1,%2,%3};"
                 : "+f"(d[0]), "+f"(d[1]), "+f"(d[2]), "+f"(d[3])
                 : "r"(a[0]), "r"(a[1]), "r"(a[2]), "r"(a[3]), "r"(b[0]), "r"(b[1]));
}
__device__ __forceinline__ void ldsm4(uint32_t* r, uint32_t a) {
    asm volatile("ldmatrix.sync.aligned.m8n8.x4.shared.b16 {%0,%1,%2,%3}, [%4];"
                 : "=r"(r[0]), "=r"(r[1]), "=r"(r[2]), "=r"(r[3]) : "r"(a));
}

// ======================= tensor-core fp16 GEMM =============================
// C[M,N](fp32) = A@B^T ; A[M][K] fp16, B stored [N][K] fp16.
// BM x BN CTA tile, warp tile 64x64, 3-stage cp.async pipeline.
#define GSTRIDE 40

template <int BM, int BN, int NT>
__global__ void __launch_bounds__(NT) mma_gemm_k(
    const __half* __restrict__ Ah, const __half* __restrict__ Bh,
    float* __restrict__ C, int Nn, int K)
{
    constexpr int APART = BM * GSTRIDE;
    constexpr int BPARTT = BN * GSTRIDE;
    constexpr int STAGE_BYTES = (APART + BPARTT) * 2;
    constexpr int ROWS_PER_STEP = NT / 4;
    constexpr int NSTEPS = (BM + BN) / ROWS_PER_STEP;
    constexpr int WN = BN / 64;                       // warps along N

    const int tid  = threadIdx.x;
    const int lane = tid & 31;
    const int wid  = tid >> 5;
    const int wm   = wid / WN;
    const int wn   = wid % WN;
    const int g    = lane >> 2;
    const int tig  = lane & 3;

    const int row0 = blockIdx.y * BM;
    const int col0 = blockIdx.x * BN;
    const int iters = K / 32;
    const int r0 = tid >> 2, s0 = tid & 3;

    const int arow = (lane & 7) + ((lane >> 3) & 1) * 8;
    const int acol = ((lane >> 4) & 1) * 8;
    const int brow = (lane & 7) + ((lane >> 4) & 1) * 8;
    const int bcol = ((lane >> 3) & 1) * 8;

    const uint32_t smbase = (uint32_t)__cvta_generic_to_shared(dynsm);
    uint32_t aoff[4], boff[4];
#pragma unroll
    for (int mi = 0; mi < 4; mi++)
        aoff[mi] = (uint32_t)(((wm * 64 + mi * 16 + arow) * GSTRIDE + acol) * 2);
#pragma unroll
    for (int nj = 0; nj < 4; nj++)
        boff[nj] = (uint32_t)(((wn * 64 + nj * 16 + brow) * GSTRIDE + bcol) * 2);

    float acc[4][8][4];
#pragma unroll
    for (int mi = 0; mi < 4; mi++)
#pragma unroll
        for (int ni = 0; ni < 8; ni++)
#pragma unroll
            for (int q = 0; q < 4; q++) acc[mi][ni][q] = 0.f;

    auto load_tiles = [&](int buf, int it) {
        const int k0 = it * 32;
        uint32_t b = smbase + buf * STAGE_BYTES;
#pragma unroll
        for (int j = 0; j < NSTEPS; j++) {
            int r = r0 + j * ROWS_PER_STEP;
            if (r < BM) {
                uint32_t soff = (uint32_t)(r * GSTRIDE + s0 * 8) * 2;
                size_t ga = (size_t)(row0 + r) * K + k0 + s0 * 8;
                cp16(b + soff, Ah + ga, true);
            } else {
                int rb = r - BM;
                uint32_t soff = (uint32_t)((BM + rb) * GSTRIDE + s0 * 8) * 2;
                int nb = col0 + rb;
                bool p = nb < Nn;
                size_t gb = (size_t)(p ? nb : 0) * K + k0 + s0 * 8;
                cp16(b + soff, Bh + gb, p);
            }
        }
        asm volatile("cp.async.commit_group;\n" ::);
    };

    load_tiles(0, 0);
    load_tiles(1, 1);

    for (int it = 0; it < iters; it++) {
        asm volatile("cp.async.wait_group 1;\n" ::);
        __syncthreads();

        const int buf = it % 3;
        uint32_t bA  = smbase + buf * STAGE_BYTES;
        uint32_t bBh = bA + APART * 2;

#pragma unroll
        for (int kk = 0; kk < 2; kk++) {
            const uint32_t kof = kk * 32;
            uint32_t ah[4][4], bh[4][4];
#pragma unroll
            for (int mi = 0; mi < 4; mi++) ldsm4(ah[mi], bA + aoff[mi] + kof);
#pragma unroll
            for (int nj = 0; nj < 4; nj++) ldsm4(bh[nj], bBh + boff[nj] + kof);

#pragma unroll
            for (int mi = 0; mi < 4; mi++)
#pragma unroll
                for (int ni = 0; ni < 8; ni++)
                    mma_fp16(acc[mi][ni], ah[mi], &bh[ni >> 1][(ni & 1) * 2]);
        }

        const int nx = it + 2;
        if (nx < iters) {
            load_tiles(nx % 3, nx);
        } else {
            asm volatile("cp.async.commit_group;\n" ::);
        }
    }

#pragma unroll
    for (int mi = 0; mi < 4; mi++) {
        int ra = row0 + wm * 64 + mi * 16 + g;
#pragma unroll
        for (int ni = 0; ni < 8; ni++) {
            int c = col0 + wn * 64 + ni * 8 + 2 * tig;
            if (c < Nn) {
                *reinterpret_cast<float2*>(&C[(size_t)ra * Nn + c]) =
                    make_float2(acc[mi][ni][0], acc[mi][ni][1]);
                *reinterpret_cast<float2*>(&C[(size_t)(ra + 8) * Nn + c]) =
                    make_float2(acc[mi][ni][2], acc[mi][ni][3]);
            }
        }
    }
}

#define SMEM_G1 (3 * (128 * GSTRIDE + 256 * GSTRIDE) * 2)   // 92160
#define SMEM_G2 (3 * (128 * GSTRIDE + 128 * GSTRIDE) * 2)   // 61440

// ---------------- conv: smem-tiled depthwise causal conv + silu -------------
__global__ void __launch_bounds__(256) conv_k(
    const float* __restrict__ conv_w, const float* __restrict__ conv_b)
{
    __shared__ float st[35][128];
    const int c0 = blockIdx.x * 128;
    const int b  = blockIdx.y >> 7;
    const int lg = blockIdx.y & 127;
    const int l0 = lg * 32;

    for (int i = threadIdx.x; i < 35 * 128; i += 256) {
        int r = i >> 7, cc = i & 127;
        int ls = l0 - 3 + r;
        st[r][cc] = (ls >= 0) ? g_zx[(size_t)(b * LL + ls) * DPROJ + DIN + c0 + cc] : 0.f;
    }
    __syncthreads();

    for (int i = threadIdx.x; i < 32 * 128; i += 256) {
        int r = i >> 7, cc = i & 127;
        int c = c0 + cc;
        float w0 = conv_w[c * 4 + 0], w1 = conv_w[c * 4 + 1];
        float w2 = conv_w[c * 4 + 2], w3 = conv_w[c * 4 + 3];
        float acc = conv_b[c];
        acc = fmaf(st[r + 0][cc], w0, acc);
        acc = fmaf(st[r + 1][cc], w1, acc);
        acc = fmaf(st[r + 2][cc], w2, acc);
        acc = fmaf(st[r + 3][cc], w3, acc);
        g_xbc[(size_t)(b * LL + l0 + r) * CONVD + c] = acc / (1.f + __expf(-acc));
    }
}

// ---------------- dt prep ----------------------------------------------------
__global__ void __launch_bounds__(256) dt_k(
    const float* __restrict__ dt_bias, const float* __restrict__ A_log)
{
    int i = blockIdx.x * blockDim.x + threadIdx.x;
    if (i >= BLROWS * NH) return;
    int row = i / NH, h = i % NH;
    float v = g_zx[(size_t)row * DPROJ + (DIN + CONVD) + h] + dt_bias[h];
    float sp = (v > 20.f) ? v : log1pf(expf(v));
    float Ah = -expf(A_log[h]);
    g_dt[i] = sp;
    g_dA[i] = expf(sp * Ah);
}

// ======================= SSD scan (tensor-core) =============================
#define SSD1_SMEM 36608
__global__ void __launch_bounds__(128) ssd1_k()
{
    const int bid = blockIdx.x;
    const int h = bid % NH;
    const int c = (bid / NH) % NCHUNK;
    const int b = bid / (NH * NCHUNK);
    const int rowbase = b * LL + c * CHUNK;
    __half* sBt = reinterpret_cast<__half*>(dynsm);            // [64 n][72 s]
    __half* sUt = reinterpret_cast<__half*>(dynsm + 9216);     // [64 p][72 s]
    float* sdt  = reinterpret_cast<float*>(dynsm + 18432);
    float* sdA  = reinterpret_cast<float*>(dynsm + 18688);
    float* rsf  = reinterpret_cast<float*>(dynsm + 18944);
    float* hb   = reinterpret_cast<float*>(dynsm + 19200);     // [64][68]
    const int tid = threadIdx.x, lane = tid & 31, w = tid >> 5;

    if (tid < 64) {
        sdt[tid] = g_dt[(size_t)(rowbase + tid) * NH + h];
        sdA[tid] = g_dA[(size_t)(rowbase + tid) * NH + h];
    }
    __syncthreads();
    if (tid < 64) {
        float rr = 1.f;
        for (int j = 63; j > tid; j--) rr *= sdA[j];
        rsf[tid] = rr;
    }
    __syncthreads();
    for (int i = tid; i < 4096; i += 128) {
        int s = i >> 6, n = i & 63;
        const float* xr = g_xbc + (size_t)(rowbase + s) * CONVD;
        sBt[n * 72 + s] = __float2half(rsf[s] * xr[DIN + n]);
        sUt[n * 72 + s] = __float2half(sdt[s] * xr[h * HD + n]);
    }
    __syncthreads();

    const int g = lane >> 2, tig = lane & 3;
    const int arow = (lane & 7) + ((lane >> 3) & 1) * 8;
    const int acol = ((lane >> 4) & 1) * 8;
    const int brow = (lane & 7) + ((lane >> 4) & 1) * 8;
    const int bcol = ((lane >> 3) & 1) * 8;
    const int tb = w * 16;
    const uint32_t base = (uint32_t)__cvta_generic_to_shared(dynsm);

    float acc[8][4];
#pragma unroll
    for (int i = 0; i < 8; i++)
#pragma unroll
        for (int q = 0; q < 4; q++) acc[i][q] = 0.f;
#pragma unroll
    for (int k = 0; k < 4; k++) {
        uint32_t af[4];
        ldsm4(af, base + (uint32_t)(((tb + arow) * 72 + k * 16 + acol) * 2));
#pragma unroll
        for (int pj = 0; pj < 4; pj++) {
            uint32_t bf[4];
            ldsm4(bf, base + 9216u + (uint32_t)(((pj * 16 + brow) * 72 + k * 16 + bcol) * 2));
            mma_fp16(acc[pj * 2 + 0], af, &bf[0]);
            mma_fp16(acc[pj * 2 + 1], af, &bf[2]);
        }
    }
    const int n0 = tb + g, n1 = tb + g + 8;
#pragma unroll
    for (int ni = 0; ni < 8; ni++) {
        int p0 = ni * 8 + 2 * tig;
        hb[n0 * 68 + p0]     = acc[ni][0];
        hb[n0 * 68 + p0 + 1] = acc[ni][1];
        hb[n1 * 68 + p0]     = acc[ni][2];
        hb[n1 * 68 + p0 + 1] = acc[ni][3];
    }
    __syncthreads();
    const size_t bhc = ((size_t)(b * NH + h)) * NCHUNK + c;
    float* Sp = g_S + bhc * DS * HD;
    for (int i = tid; i < 1024; i += 128) {
        int n = i >> 4, q = i & 15;
        *reinterpret_cast<float4*>(Sp + n * HD + q * 4) =
            *reinterpret_cast<const float4*>(hb + n * 68 + q * 4);
    }
    if (tid == 0) g_P[bhc] = rsf[0] * sdA[0];
}

// ---------------- combine (float4) -------------------------------------------
__global__ void __launch_bounds__(256) combine_k()
{
    const int i = blockIdx.x * blockDim.x + threadIdx.x;
    if (i >= BB * NH * DS * HD / 4) return;
    const int pn4 = i % (DS * HD / 4);
    const int bh = i / (DS * HD / 4);
    float4 hp = make_float4(0.f, 0.f, 0.f, 0.f);
    const float* P = g_P + bh * NCHUNK;
    const size_t base = (size_t)bh * NCHUNK * DS * HD + pn4 * 4;
    for (int c = 0; c < NCHUNK; c++) {
        *reinterpret_cast<float4*>(g_hini + base + (size_t)c * DS * HD) = hp;
        float4 s = *reinterpret_cast<const float4*>(g_S + base + (size_t)c * DS * HD);
        float pc = P[c];
        hp.x = fmaf(hp.x, pc, s.x);
        hp.y = fmaf(hp.y, pc, s.y);
        hp.z = fmaf(hp.z, pc, s.z);
        hp.w = fmaf(hp.w, pc, s.w);
    }
}

#define SSD2_SMEM 71424
__global__ void __launch_bounds__(128) ssd2_k(const float* __restrict__ Dp)
{
    const int bid = blockIdx.x;
    const int h = bid % NH;
    const int c = (bid / NH) % NCHUNK;
    const int b = bid / (NH * NCHUNK);
    const int rowbase = b * LL + c * CHUNK;
    const size_t bhc = ((size_t)(b * NH + h)) * NCHUNK + c;

    __half* sB  = reinterpret_cast<__half*>(dynsm);             // [64 t][72 n]
    __half* sC  = reinterpret_cast<__half*>(dynsm + 9216);      // [64 t][72 n]
    float*  sR  = reinterpret_cast<float*>(dynsm + 18432);      // [64 t][68 s]
    __half* sGE = reinterpret_cast<__half*>(dynsm + 35840);     // [64 t][136] A'
    __half* sBp = reinterpret_cast<__half*>(dynsm + 53248);     // [64 p][136] B'
    float*  sdt = reinterpret_cast<float*>(dynsm + 70656);
    float*  sdA = reinterpret_cast<float*>(dynsm + 70912);
    float*  scum= reinterpret_cast<float*>(dynsm + 71168);
    float*  ybuf= reinterpret_cast<float*>(dynsm);              // alias [64][68]
    const int tid = threadIdx.x, lane = tid & 31, w = tid >> 5;

    if (tid < 64) {
        sdt[tid] = g_dt[(size_t)(rowbase + tid) * NH + h];
        sdA[tid] = g_dA[(size_t)(rowbase + tid) * NH + h];
    }
    __syncthreads();
    if (tid < 64) {
        int t = tid;
        float rr = 1.f;
        sR[t * 68 + t] = 1.f;
        for (int s = t - 1; s >= 0; s--) { rr *= sdA[s + 1]; sR[t * 68 + s] = rr; }
        scum[t] = rr * sdA[0];
    }
    // vectorized B/C staging (contiguous in n)
    for (int i = tid; i < 1024; i += 128) {
        int t = i >> 4, q = i & 15;
        const float* xr = g_xbc + (size_t)(rowbase + t) * CONVD;
        float4 vb = *reinterpret_cast<const float4*>(xr + DIN + q * 4);
        float4 vc = *reinterpret_cast<const float4*>(xr + DIN + DS + q * 4);
        __half2 b0 = __floats2half2_rn(vb.x, vb.y), b1 = __floats2half2_rn(vb.z, vb.w);
        __half2 c0 = __floats2half2_rn(vc.x, vc.y), c1 = __floats2half2_rn(vc.z, vc.w);
        *reinterpret_cast<__half2*>(sB + t * 72 + q * 4)     = b0;
        *reinterpret_cast<__half2*>(sB + t * 72 + q * 4 + 2) = b1;
        *reinterpret_cast<__half2*>(sC + t * 72 + q * 4)     = c0;
        *reinterpret_cast<__half2*>(sC + t * 72 + q * 4 + 2) = c1;
    }
    __syncthreads();
    for (int i = tid; i < 4096; i += 128) {
        int s = i >> 6, p = i & 63;
        const float* xr = g_xbc + (size_t)(rowbase + s) * CONVD;
        sBp[p * 136 + s] = __float2half(sdt[s] * xr[h * HD + p]);
    }
    {
        const float* hv = g_hini + bhc * DS * HD;
        for (int i = tid; i < 4096; i += 128) {
            int n = i >> 6, p = i & 63;
            sBp[p * 136 + 64 + n] = __float2half(hv[n * HD + p]);
        }
    }
    __syncthreads();

    const int g = lane >> 2, tig = lane & 3;
    const int arow = (lane & 7) + ((lane >> 3) & 1) * 8;
    const int acol = ((lane >> 4) & 1) * 8;
    const int brow = (lane & 7) + ((lane >> 4) & 1) * 8;
    const int bcol = ((lane >> 3) & 1) * 8;
    const int tb = w * 16;
    const uint32_t base = (uint32_t)__cvta_generic_to_shared(dynsm);

    // S = C @ B^T
    float accS[8][4];
#pragma unroll
    for (int i = 0; i < 8; i++)
#pragma unroll
        for (int q = 0; q < 4; q++) accS[i][q] = 0.f;
#pragma unroll
    for (int k = 0; k < 4; k++) {
        uint32_t af[4];
        ldsm4(af, base + 9216u + (uint32_t)(((tb + arow) * 72 + k * 16 + acol) * 2));
#pragma unroll
        for (int nj = 0; nj < 4; nj++) {
            uint32_t bf[4];
            ldsm4(bf, base + (uint32_t)(((nj * 16 + brow) * 72 + k * 16 + bcol) * 2));
            mma_fp16(accS[nj * 2 + 0], af, &bf[0]);
            mma_fp16(accS[nj * 2 + 1], af, &bf[2]);
        }
    }
    const int t0 = tb + g, t1 = tb + g + 8;
#pragma unroll
    for (int ni = 0; ni < 8; ni++) {
        int s0 = ni * 8 + 2 * tig;
        float r00 = (s0     <= t0) ? sR[t0 * 68 + s0]     : 0.f;
        float r01 = (s0 + 1 <= t0) ? sR[t0 * 68 + s0 + 1] : 0.f;
        float r10 = (s0     <= t1) ? sR[t1 * 68 + s0]     : 0.f;
        float r11 = (s0 + 1 <= t1) ? sR[t1 * 68 + s0 + 1] : 0.f;
        __half2 h0 = __floats2half2_rn(accS[ni][0] * r00, accS[ni][1] * r01);
        __half2 h1 = __floats2half2_rn(accS[ni][2] * r10, accS[ni][3] * r11);
        *reinterpret_cast<__half2*>(sGE + t0 * 136 + s0) = h0;
        *reinterpret_cast<__half2*>(sGE + t1 * 136 + s0) = h1;
    }
    // Ce = cum_t * C (cols 64..127 of A'), vectorized
    for (int i = tid; i < 1024; i += 128) {
        int t = i >> 4, q = i & 15;
        float sc = scum[t];
        __half2 v0 = *reinterpret_cast<const __half2*>(sC + t * 72 + q * 4);
        __half2 v1 = *reinterpret_cast<const __half2*>(sC + t * 72 + q * 4 + 2);
        float2 f0 = __half22float2(v0), f1 = __half22float2(v1);
        *reinterpret_cast<__half2*>(sGE + t * 136 + 64 + q * 4) =
            __floats2half2_rn(f0.x * sc, f0.y * sc);
        *reinterpret_cast<__half2*>(sGE + t * 136 + 64 + q * 4 + 2) =
            __floats2half2_rn(f1.x * sc, f1.y * sc);
    }
    __syncthreads();

    // Y = A' @ B'^T  (k = 128)
    float accY[8][4];
#pragma unroll
    for (int i = 0; i < 8; i++)
#pragma unroll
        for (int q = 0; q < 4; q++) accY[i][q] = 0.f;
#pragma unroll
    for (int k = 0; k < 8; k++) {
        uint32_t af[4];
        ldsm4(af, base + 35840u + (uint32_t)(((tb + arow) * 136 + k * 16 + acol) * 2));
#pragma unroll
        for (int pj = 0; pj < 4; pj++) {
            uint32_t bf[4];
            ldsm4(bf, base + 53248u + (uint32_t)(((pj * 16 + brow) * 136 + k * 16 + bcol) * 2));
            mma_fp16(accY[pj * 2 + 0], af, &bf[0]);
            mma_fp16(accY[pj * 2 + 1], af, &bf[2]);
        }
    }
    __syncthreads();   // done reading sB/sC region before ybuf alias write
#pragma unroll
    for (int ni = 0; ni < 8; ni++) {
        int p0 = ni * 8 + 2 * tig;
        ybuf[t0 * 68 + p0]     = accY[ni][0];
        ybuf[t0 * 68 + p0 + 1] = accY[ni][1];
        ybuf[t1 * 68 + p0]     = accY[ni][2];
        ybuf[t1 * 68 + p0 + 1] = accY[ni][3];
    }
    __syncthreads();
    const float Dh = Dp[h];
    for (int i = tid; i < 1024; i += 128) {
        int t = i >> 4, q = i & 15;
        int p = q * 4;
        float4 yv = *reinterpret_cast<const float4*>(ybuf + t * 68 + p);
        float4 xv = *reinterpret_cast<const float4*>(
            g_xbc + (size_t)(rowbase + t) * CONVD + h * HD + p);
        yv.x = fmaf(Dh, xv.x, yv.x);
        yv.y = fmaf(Dh, xv.y, yv.y);
        yv.z = fmaf(Dh, xv.z, yv.z);
        yv.w = fmaf(Dh, xv.w, yv.w);
        *reinterpret_cast<float4*>(g_y + (size_t)(rowbase + t) * DIN + h * HD + p) = yv;
    }
}

// ---------------- gate + RMSNorm + convert to fp16 --------------------------
__global__ void __launch_bounds__(512) gatenorm_k(const float* __restrict__ norm_w)
{
    const int row = blockIdx.x;
    const float* zrow = g_zx + (size_t)row * DPROJ;
    const float* yrow = g_y + (size_t)row * DIN;

    float gv[3];
    float ss = 0.f;
#pragma unroll
    for (int j = 0; j < 3; j++) {
        int i = threadIdx.x + j * 512;
        float z = zrow[i];
        float gg = yrow[i] * (z / (1.f + __expf(-z)));
        gv[j] = gg;
        ss = fmaf(gg, gg, ss);
    }

    __shared__ float red[16];
#pragma unroll
    for (int o = 16; o; o >>= 1) ss += __shfl_xor_sync(0xffffffffu, ss, o);
    if ((threadIdx.x & 31) == 0) red[threadIdx.x >> 5] = ss;
    __syncthreads();
    if (threadIdx.x < 16) {
        float v = red[threadIdx.x];
#pragma unroll
        for (int o = 8; o; o >>= 1) v += __shfl_xor_sync(0x0000ffffu, v, o);
        if (threadIdx.x == 0) red[0] = v;
    }
    __syncthreads();
    const float scale = rsqrtf(red[0] / (float)DIN + 1e-5f);
#pragma unroll
    for (int j = 0; j < 3; j++) {
        int i = threadIdx.x + j * 512;
        float v = gv[j] * scale * norm_w[i];
        g_yh[(size_t)row * DIN + i] = __float2half(v);
    }
}

// ---------------- launch ----------------------------------------------------
extern "C" void kernel_launch(void* const* d_in, const int* in_sizes, int n_in,
                              void* d_out, int out_size)
{
    const float* x       = (const float*)d_in[0];
    const float* W_in    = (const float*)d_in[1];
    const float* conv_w  = (const float*)d_in[2];
    const float* conv_b  = (const float*)d_in[3];
    const float* dt_bias = (const float*)d_in[4];
    const float* A_log   = (const float*)d_in[5];
    const float* Dp      = (const float*)d_in[6];
    const float* norm_w  = (const float*)d_in[7];
    const float* W_out   = (const float*)d_in[8];
    float* out           = (float*)d_out;

    float* zx = nullptr;
    __half *xh, *wih, *yh, *woh;
    cudaGetSymbolAddress((void**)&zx,  g_zx);
    cudaGetSymbolAddress((void**)&xh,  g_xh);
    cudaGetSymbolAddress((void**)&wih, g_wih);
    cudaGetSymbolAddress((void**)&yh,  g_yh);
    cudaGetSymbolAddress((void**)&woh, g_woh);

    static bool attr_set = false;
    if (!attr_set) {
        cudaFuncSetAttribute((const void*)mma_gemm_k<128, 256, 256>,
                             cudaFuncAttributeMaxDynamicSharedMemorySize, SMEM_G1);
        cudaFuncSetAttribute((const void*)mma_gemm_k<128, 128, 128>,
                             cudaFuncAttributeMaxDynamicSharedMemorySize, SMEM_G2);
        cudaFuncSetAttribute(ssd1_k, cudaFuncAttributeMaxDynamicSharedMemorySize,
                             SSD1_SMEM);
        cudaFuncSetAttribute(ssd2_k, cudaFuncAttributeMaxDynamicSharedMemorySize,
                             SSD2_SMEM);
        attr_set = true;
    }

    // 0) convert inputs to fp16
    {
        int n4 = BLROWS * DM / 4;
        split_x_k<<<(n4 + 255) / 256, 256>>>(x, xh, n4);
        tsplit_k<<<dim3(DM / 32, (DPROJ + 31) / 32), 256>>>(W_in, wih, DM, DPROJ);
        tsplit_k<<<dim3(DIN / 32, DM / 32), 256>>>(W_out, woh, DIN, DM);
    }

    // 1) zxbcdt = x @ W_in   (128x256 CTA, 64x64 warp tiles)
    mma_gemm_k<128, 256, 256><<<dim3((DPROJ + 255) / 256, BLROWS / 128), 256, SMEM_G1>>>(
        xh, wih, zx, DPROJ, DM);

    // 2) conv + silu ; dt prep
    conv_k<<<dim3(CONVD / 128, BB * (LL / 32)), 256>>>(conv_w, conv_b);
    dt_k<<<(BLROWS * NH + 255) / 256, 256>>>(dt_bias, A_log);

    // 3) SSD chunked scan (tensor cores)
    {
        int blocks = BB * NCHUNK * NH;   // 3072
        ssd1_k<<<blocks, 128, SSD1_SMEM>>>();
        int nq = BB * NH * DS * HD / 4;
        combine_k<<<(nq + 255) / 256, 256>>>();
        ssd2_k<<<blocks, 128, SSD2_SMEM>>>(Dp);
    }

    // 4) gate + RMSNorm + fp16 convert
    gatenorm_k<<<BLROWS, 512>>>(norm_w);

    // 5) out = y @ W_out   (128x128 CTA, 64x64 warp tiles)
    mma_gemm_k<128, 128, 128><<<dim3(DM / 128, BLROWS / 128), 128, SMEM_G2>>>(
        yh, woh, out, DM, DIN);
}